// round 5
// baseline (speedup 1.0000x reference)
#include <cuda_runtime.h>

// StochasticAttention collapses algebraically:
//   attention[b,q,v] = sum_f x[b,v,f] * (sum_d w_value[d,f])   (independent of q)
//
// k_wsum: 32 blocks compute wsum[f] = sum_d w_value[d,f] -> g_wsum (fast, parallel).
// k_main: 512 CTAs x 256 threads; CTA = (b, 32-v chunk). 3-4 CTAs/SM co-resident,
//         so load phases of some CTAs overlap store phases of others (full-duplex HBM)
//         without any intra-block pipelining or barrier lockstep.

#define FDIM 1024
#define BDIM 16
#define DDIM 64

__device__ __align__(16) float g_wsum[FDIM];

// ---- wsum = column-sum of w_value [D, F] ----
// Block j owns 8 float4 columns (32 floats). Thread (dg, col): sums 2 d-rows.
__global__ void k_wsum(const float* __restrict__ w_value) {
    __shared__ __align__(16) float4 part[32][8];
    const int col  = threadIdx.x & 7;
    const int dg   = threadIdx.x >> 3;              // 0..31
    const int gcol = blockIdx.x * 8 + col;          // global float4 column
    const float4* w4 = reinterpret_cast<const float4*>(w_value);
    float4 a = w4[(size_t)(2 * dg)     * (FDIM / 4) + gcol];
    float4 b = w4[(size_t)(2 * dg + 1) * (FDIM / 4) + gcol];
    float4 s;
    s.x = a.x + b.x; s.y = a.y + b.y; s.z = a.z + b.z; s.w = a.w + b.w;
    part[dg][col] = s;
    __syncthreads();
    if (threadIdx.x < 8) {
        float4 acc = part[0][threadIdx.x];
#pragma unroll
        for (int k = 1; k < 32; ++k) {
            float4 p = part[k][threadIdx.x];
            acc.x += p.x; acc.y += p.y; acc.z += p.z; acc.w += p.w;
        }
        reinterpret_cast<float4*>(g_wsum)[blockIdx.x * 8 + threadIdx.x] = acc;
    }
}

// ---- main: dots + broadcast ----
__global__ __launch_bounds__(256)
void k_main(const float* __restrict__ x, float* __restrict__ out) {
    __shared__ __align__(16) float4 s_wsum[FDIM / 4];  // 4 KB
    __shared__ __align__(16) float  s_row[32];

    const int tid  = threadIdx.x;
    const int warp = tid >> 5;          // 0..7
    const int lane = tid & 31;
    const int b     = blockIdx.x >> 5;  // batch
    const int chunk = blockIdx.x & 31;  // 32-v chunk within batch

    s_wsum[tid] = reinterpret_cast<const float4*>(g_wsum)[tid];
    __syncthreads();

    // Each warp computes 4 row-dots: row = chunk*32 + warp*4 + r
    const float4* x4 = reinterpret_cast<const float4*>(x);
    const unsigned rowbase = ((unsigned)b << 10) + ((unsigned)chunk << 5);
#pragma unroll
    for (int r = 0; r < 4; ++r) {
        const float4* xr = x4 + (size_t)(rowbase + warp * 4 + r) * (FDIM / 4);
        float4 a[8];
#pragma unroll
        for (int t = 0; t < 8; ++t) a[t] = xr[t * 32 + lane];
        float acc = 0.f;
#pragma unroll
        for (int t = 0; t < 8; ++t) {
            float4 w = s_wsum[t * 32 + lane];
            acc += a[t].x * w.x + a[t].y * w.y + a[t].z * w.z + a[t].w * w.w;
        }
#pragma unroll
        for (int off = 16; off; off >>= 1)
            acc += __shfl_xor_sync(0xffffffffu, acc, off);
        if (lane == 0) s_row[warp * 4 + r] = acc;
    }
    __syncthreads();

    // Broadcast the 32 v-values across all 1024 q.
    // Lane layout: col = lane&7 selects the float4 within the 32-v segment,
    // qsub = lane>>3 selects one of 4 q-rows; each 8-lane group writes 128B contiguous.
    const float4 val = reinterpret_cast<const float4*>(s_row)[lane & 7];
    float4* out4 = reinterpret_cast<float4*>(out);
    const unsigned obase = ((unsigned)b << 18) + ((unsigned)chunk << 3) + (unsigned)(lane & 7);
    const unsigned q0 = (unsigned)(warp * 4 + (lane >> 3));
#pragma unroll 8
    for (int i = 0; i < 32; ++i) {
        unsigned q = (unsigned)i * 32u + q0;
        out4[obase + q * (FDIM / 4)] = val;
    }
}

extern "C" void kernel_launch(void* const* d_in, const int* in_sizes, int n_in,
                              void* d_out, int out_size) {
    const float* x       = (const float*)d_in[0];  // [B,F,F]
    const float* w_value = (const float*)d_in[4];  // [D,F]
    float* out = (float*)d_out;                    // [B,F,F]
    (void)in_sizes; (void)n_in; (void)out_size;

    k_wsum<<<32, 256>>>(w_value);
    k_main<<<BDIM * 32, 256>>>(x, out);
}

// round 6
// speedup vs baseline: 1.0278x; 1.0278x over previous
#include <cuda_runtime.h>

// StochasticAttention collapses algebraically:
//   attention[b,q,v] = sum_f x[b,v,f] * (sum_d w_value[d,f])   (independent of q)
//
// k_wsum: 32 blocks compute wsum[f] = sum_d w_value[d,f] -> g_wsum.
// k_main: 1024 CTAs x 256 threads; CTA = (b, 16-v chunk). ~7 CTAs/SM co-resident
//         for high occupancy; load/store phases of different CTAs overlap.

#define FDIM 1024
#define BDIM 16
#define DDIM 64

__device__ __align__(16) float g_wsum[FDIM];

// ---- wsum = column-sum of w_value [D, F] ----
__global__ void k_wsum(const float* __restrict__ w_value) {
    __shared__ __align__(16) float4 part[32][8];
    const int col  = threadIdx.x & 7;
    const int dg   = threadIdx.x >> 3;              // 0..31
    const int gcol = blockIdx.x * 8 + col;
    const float4* w4 = reinterpret_cast<const float4*>(w_value);
    float4 a = w4[(size_t)(2 * dg)     * (FDIM / 4) + gcol];
    float4 b = w4[(size_t)(2 * dg + 1) * (FDIM / 4) + gcol];
    float4 s;
    s.x = a.x + b.x; s.y = a.y + b.y; s.z = a.z + b.z; s.w = a.w + b.w;
    part[dg][col] = s;
    __syncthreads();
    if (threadIdx.x < 8) {
        float4 acc = part[0][threadIdx.x];
#pragma unroll
        for (int k = 1; k < 32; ++k) {
            float4 p = part[k][threadIdx.x];
            acc.x += p.x; acc.y += p.y; acc.z += p.z; acc.w += p.w;
        }
        reinterpret_cast<float4*>(g_wsum)[blockIdx.x * 8 + threadIdx.x] = acc;
    }
}

// ---- main: 16 row-dots + broadcast across q ----
__global__ __launch_bounds__(256)
void k_main(const float* __restrict__ x, float* __restrict__ out) {
    __shared__ __align__(16) float4 s_wsum[FDIM / 4];  // 4 KB
    __shared__ __align__(16) float  s_row[16];

    const int tid  = threadIdx.x;
    const int warp = tid >> 5;          // 0..7
    const int lane = tid & 31;
    const int b     = blockIdx.x >> 6;  // batch (0..15)
    const int chunk = blockIdx.x & 63;  // 16-v chunk within batch

    s_wsum[tid] = reinterpret_cast<const float4*>(g_wsum)[tid];
    __syncthreads();

    // Warp w computes rows chunk*16 + 2w and 2w+1.
    const float4* x4 = reinterpret_cast<const float4*>(x);
    const unsigned rowbase = ((unsigned)b << 10) + ((unsigned)chunk << 4);
#pragma unroll
    for (int r = 0; r < 2; ++r) {
        const float4* xr = x4 + (size_t)(rowbase + warp * 2 + r) * (FDIM / 4);
        float4 a[8];
#pragma unroll
        for (int t = 0; t < 8; ++t) a[t] = xr[t * 32 + lane];
        float acc = 0.f;
#pragma unroll
        for (int t = 0; t < 8; ++t) {
            float4 w = s_wsum[t * 32 + lane];
            acc += a[t].x * w.x + a[t].y * w.y + a[t].z * w.z + a[t].w * w.w;
        }
#pragma unroll
        for (int off = 16; off; off >>= 1)
            acc += __shfl_xor_sync(0xffffffffu, acc, off);
        if (lane == 0) s_row[warp * 2 + r] = acc;
    }
    __syncthreads();

    // Broadcast 16 v-values across all 1024 q.
    // lane&3 = float4 column within the 16-v segment; lane>>2 = q-sub (0..7).
    // Warp covers 8 q per iteration; block covers 64 q; 16 iterations.
    const float4 val = reinterpret_cast<const float4*>(s_row)[lane & 3];
    const unsigned q0 = (unsigned)(warp * 8 + (lane >> 2));
    float4* p = reinterpret_cast<float4*>(out)
              + ((size_t)b << 18) + ((size_t)chunk << 2) + (size_t)(lane & 3)
              + (size_t)q0 * (FDIM / 4);
#pragma unroll
    for (int i = 0; i < 16; ++i) {
        *p = val;
        p += 64 * (FDIM / 4);   // advance 64 q-rows
    }
}

extern "C" void kernel_launch(void* const* d_in, const int* in_sizes, int n_in,
                              void* d_out, int out_size) {
    const float* x       = (const float*)d_in[0];  // [B,F,F]
    const float* w_value = (const float*)d_in[4];  // [D,F]
    float* out = (float*)d_out;                    // [B,F,F]
    (void)in_sizes; (void)n_in; (void)out_size;

    k_wsum<<<32, 256>>>(w_value);
    k_main<<<BDIM * 64, 256>>>(x, out);
}

// round 9
// speedup vs baseline: 1.1525x; 1.1212x over previous
#include <cuda_runtime.h>
#include <cstdint>

// StochasticAttention collapses algebraically:
//   attention[b,q,v] = sum_f x[b,v,f] * (sum_d w_value[d,f])   (independent of q)
//
// Steady-state optimization: graph replays are back-to-back; out (64MB) is fully
// rewritten each replay. Pin out in L2 (evict_last stores) and stream x through
// (evict_first loads). sm_100a requires 256-bit accesses for these hints, so both
// the x loads and the out stores are 32B per lane (v4.b64).

#define FDIM 1024
#define BDIM 16
#define DDIM 64

struct U4 { uint64_t a, b, c, d; };

__device__ __forceinline__ U4 ldg_stream32(const void* p) {
    U4 v;
    asm volatile("ld.global.nc.L2::evict_first.v4.b64 {%0,%1,%2,%3}, [%4];"
                 : "=l"(v.a), "=l"(v.b), "=l"(v.c), "=l"(v.d) : "l"(p));
    return v;
}
__device__ __forceinline__ void stg_keep32(void* p, float4 v0, float4 v1) {
    uint64_t a = ((uint64_t)__float_as_uint(v0.y) << 32) | __float_as_uint(v0.x);
    uint64_t b = ((uint64_t)__float_as_uint(v0.w) << 32) | __float_as_uint(v0.z);
    uint64_t c = ((uint64_t)__float_as_uint(v1.y) << 32) | __float_as_uint(v1.x);
    uint64_t d = ((uint64_t)__float_as_uint(v1.w) << 32) | __float_as_uint(v1.z);
    asm volatile("st.global.L2::evict_last.v4.b64 [%0], {%1,%2,%3,%4};"
                 :: "l"(p), "l"(a), "l"(b), "l"(c), "l"(d) : "memory");
}
__device__ __forceinline__ float flo(uint64_t u) { return __uint_as_float((unsigned)u); }
__device__ __forceinline__ float fhi(uint64_t u) { return __uint_as_float((unsigned)(u >> 32)); }

__global__ __launch_bounds__(1024, 1)
void k_fused(const float* __restrict__ x,
             const float* __restrict__ w_value,
             float* __restrict__ out) {
    __shared__ __align__(16) float4 s_part[4][FDIM / 4];  // 16 KB
    __shared__ __align__(16) float4 s_wsum[FDIM / 4];     // 4 KB
    __shared__ __align__(16) float  s_row[4][32];

    const int tid  = threadIdx.x;
    const int warp = tid >> 5;
    const int lane = tid & 31;
    const int b     = blockIdx.x >> 3;
    const int chunk = blockIdx.x & 7;

    const char* xbytes = reinterpret_cast<const char*>(x);
    const unsigned rowbase = ((unsigned)b << 10) + ((unsigned)chunk << 7);

    // ---- Prefetch sub-chunk 0: row rowbase+warp, 4 x 32B per lane ----
    U4 a[4];
    {
        const char* xr = xbytes + (size_t)(rowbase + warp) * (FDIM * 4);
#pragma unroll
        for (int t = 0; t < 4; ++t) a[t] = ldg_stream32(xr + (t * 32 + lane) * 32);
    }

    // ---- Phase 1: wsum = column-sum of w_value [D, F] (L2-deduped) ----
    {
        const int c   = tid & 255;
        const int seg = tid >> 8;
        const float4* w4 = reinterpret_cast<const float4*>(w_value);
        float4 acc = make_float4(0.f, 0.f, 0.f, 0.f);
#pragma unroll
        for (int d = 0; d < DDIM / 4; ++d) {
            float4 v = w4[(size_t)(seg * (DDIM / 4) + d) * (FDIM / 4) + c];
            acc.x += v.x; acc.y += v.y; acc.z += v.z; acc.w += v.w;
        }
        s_part[seg][c] = acc;
    }
    __syncthreads();
    if (tid < FDIM / 4) {
        float4 p0 = s_part[0][tid], p1 = s_part[1][tid];
        float4 p2 = s_part[2][tid], p3 = s_part[3][tid];
        float4 r;
        r.x = p0.x + p1.x + p2.x + p3.x;
        r.y = p0.y + p1.y + p2.y + p3.y;
        r.z = p0.z + p1.z + p2.z + p3.z;
        r.w = p0.w + p1.w + p2.w + p3.w;
        s_wsum[tid] = r;
    }
    __syncthreads();

    // ---- Pipelined sub-chunks: 32 rows each ----
    float4* out4 = reinterpret_cast<float4*>(out);
    const int qoff = lane >> 2;          // 0..7: q-row within warp's group
    const int col2 = lane & 3;           // which 32B chunk of the 128B v-segment
    const unsigned obase = ((unsigned)b << 18) + ((unsigned)chunk << 5);

#pragma unroll
    for (int s = 0; s < 4; ++s) {
        float acc = 0.f;
#pragma unroll
        for (int t = 0; t < 4; ++t) {
            const int c = t * 32 + lane;              // 32B chunk index within row
            float4 w0 = s_wsum[2 * c];
            float4 w1 = s_wsum[2 * c + 1];
            acc += flo(a[t].a) * w0.x + fhi(a[t].a) * w0.y
                 + flo(a[t].b) * w0.z + fhi(a[t].b) * w0.w
                 + flo(a[t].c) * w1.x + fhi(a[t].c) * w1.y
                 + flo(a[t].d) * w1.z + fhi(a[t].d) * w1.w;
        }
        if (s < 3) {
            const char* xr = xbytes + (size_t)(rowbase + (s + 1) * 32 + warp) * (FDIM * 4);
#pragma unroll
            for (int t = 0; t < 4; ++t) a[t] = ldg_stream32(xr + (t * 32 + lane) * 32);
        }
#pragma unroll
        for (int off = 16; off; off >>= 1)
            acc += __shfl_xor_sync(0xffffffffu, acc, off);
        if (lane == 0) s_row[s][warp] = acc;
        __syncthreads();

        // Broadcast these 32 v's across all 1024 q with 32B stores.
        // Warp: 8 q-rows/iteration (4 lanes x 32B = 128B per q-row); 4 iterations.
        const float4 v0 = reinterpret_cast<const float4*>(s_row[s])[col2 * 2];
        const float4 v1 = reinterpret_cast<const float4*>(s_row[s])[col2 * 2 + 1];
        const unsigned vbase = obase + ((unsigned)s << 3);
#pragma unroll
        for (int it = 0; it < 4; ++it) {
            unsigned q = (unsigned)it * 256u + (unsigned)warp * 8u + (unsigned)qoff;
            stg_keep32(out4 + vbase + q * (FDIM / 4) + (unsigned)(col2 * 2), v0, v1);
        }
    }
}

extern "C" void kernel_launch(void* const* d_in, const int* in_sizes, int n_in,
                              void* d_out, int out_size) {
    const float* x       = (const float*)d_in[0];  // [B,F,F]
    const float* w_value = (const float*)d_in[4];  // [D,F]
    float* out = (float*)d_out;                    // [B,F,F]
    (void)in_sizes; (void)n_in; (void)out_size;

    k_fused<<<BDIM * (FDIM / 128), 1024>>>(x, w_value, out);
}

// round 10
// speedup vs baseline: 1.2276x; 1.0652x over previous
#include <cuda_runtime.h>
#include <cstdint>

// StochasticAttention collapses algebraically:
//   attention[b,q,v] = sum_f x[b,v,f] * (sum_d w_value[d,f])   (independent of q)
//
// Steady-state: graph replays back-to-back. x (64MB) is re-READ every replay ->
// pin it in L2 (evict_last loads); out (64MB) is write-only -> stream it through
// (evict_first stores). Exactly one of the two fits in 126MB L2; pinning the
// re-read buffer converts steady-state DRAM traffic to a pure write stream.
// wsum hoisted to a tiny parallel kernel (removes 32MB of L2 reads from k_fused).

#define FDIM 1024
#define BDIM 16
#define DDIM 64

__device__ __align__(16) float g_wsum[FDIM];

struct U4 { uint64_t a, b, c, d; };

__device__ __forceinline__ U4 ldg_pin32(const void* p) {
    U4 v;
    asm volatile("ld.global.nc.L2::evict_last.v4.b64 {%0,%1,%2,%3}, [%4];"
                 : "=l"(v.a), "=l"(v.b), "=l"(v.c), "=l"(v.d) : "l"(p));
    return v;
}
__device__ __forceinline__ void stg_stream32(void* p, float4 v0, float4 v1) {
    uint64_t a = ((uint64_t)__float_as_uint(v0.y) << 32) | __float_as_uint(v0.x);
    uint64_t b = ((uint64_t)__float_as_uint(v0.w) << 32) | __float_as_uint(v0.z);
    uint64_t c = ((uint64_t)__float_as_uint(v1.y) << 32) | __float_as_uint(v1.x);
    uint64_t d = ((uint64_t)__float_as_uint(v1.w) << 32) | __float_as_uint(v1.z);
    asm volatile("st.global.L2::evict_first.v4.b64 [%0], {%1,%2,%3,%4};"
                 :: "l"(p), "l"(a), "l"(b), "l"(c), "l"(d) : "memory");
}
__device__ __forceinline__ float flo(uint64_t u) { return __uint_as_float((unsigned)u); }
__device__ __forceinline__ float fhi(uint64_t u) { return __uint_as_float((unsigned)(u >> 32)); }

// ---- wsum = column-sum of w_value [D, F] (32 blocks, parallel, ~1us) ----
__global__ void k_wsum(const float* __restrict__ w_value) {
    __shared__ __align__(16) float4 part[32][8];
    const int col  = threadIdx.x & 7;
    const int dg   = threadIdx.x >> 3;
    const int gcol = blockIdx.x * 8 + col;
    const float4* w4 = reinterpret_cast<const float4*>(w_value);
    float4 a = w4[(size_t)(2 * dg)     * (FDIM / 4) + gcol];
    float4 b = w4[(size_t)(2 * dg + 1) * (FDIM / 4) + gcol];
    float4 s;
    s.x = a.x + b.x; s.y = a.y + b.y; s.z = a.z + b.z; s.w = a.w + b.w;
    part[dg][col] = s;
    __syncthreads();
    if (threadIdx.x < 8) {
        float4 acc = part[0][threadIdx.x];
#pragma unroll
        for (int k = 1; k < 32; ++k) {
            float4 p = part[k][threadIdx.x];
            acc.x += p.x; acc.y += p.y; acc.z += p.z; acc.w += p.w;
        }
        reinterpret_cast<float4*>(g_wsum)[blockIdx.x * 8 + threadIdx.x] = acc;
    }
}

__global__ __launch_bounds__(1024, 1)
void k_fused(const float* __restrict__ x, float* __restrict__ out) {
    __shared__ __align__(16) float4 s_wsum[FDIM / 4];  // 4 KB
    __shared__ __align__(16) float  s_row[4][32];

    const int tid  = threadIdx.x;
    const int warp = tid >> 5;
    const int lane = tid & 31;
    const int b     = blockIdx.x >> 3;
    const int chunk = blockIdx.x & 7;

    const char* xbytes = reinterpret_cast<const char*>(x);
    const unsigned rowbase = ((unsigned)b << 10) + ((unsigned)chunk << 7);

    // ---- Prefetch sub-chunk 0: row rowbase+warp, 4 x 32B per lane ----
    U4 a[4];
    {
        const char* xr = xbytes + (size_t)(rowbase + warp) * (FDIM * 4);
#pragma unroll
        for (int t = 0; t < 4; ++t) a[t] = ldg_pin32(xr + (t * 32 + lane) * 32);
    }

    // ---- wsum from g_wsum (4KB, L2-hot) ----
    if (tid < FDIM / 4)
        s_wsum[tid] = reinterpret_cast<const float4*>(g_wsum)[tid];
    __syncthreads();

    // ---- Pipelined sub-chunks: 32 rows each ----
    float4* out4 = reinterpret_cast<float4*>(out);
    const int qoff = lane >> 2;
    const int col2 = lane & 3;
    const unsigned obase = ((unsigned)b << 18) + ((unsigned)chunk << 5);

#pragma unroll
    for (int s = 0; s < 4; ++s) {
        float acc = 0.f;
#pragma unroll
        for (int t = 0; t < 4; ++t) {
            const int c = t * 32 + lane;
            float4 w0 = s_wsum[2 * c];
            float4 w1 = s_wsum[2 * c + 1];
            acc += flo(a[t].a) * w0.x + fhi(a[t].a) * w0.y
                 + flo(a[t].b) * w0.z + fhi(a[t].b) * w0.w
                 + flo(a[t].c) * w1.x + fhi(a[t].c) * w1.y
                 + flo(a[t].d) * w1.z + fhi(a[t].d) * w1.w;
        }
        if (s < 3) {
            const char* xr = xbytes + (size_t)(rowbase + (s + 1) * 32 + warp) * (FDIM * 4);
#pragma unroll
            for (int t = 0; t < 4; ++t) a[t] = ldg_pin32(xr + (t * 32 + lane) * 32);
        }
#pragma unroll
        for (int off = 16; off; off >>= 1)
            acc += __shfl_xor_sync(0xffffffffu, acc, off);
        if (lane == 0) s_row[s][warp] = acc;
        __syncthreads();

        // Broadcast these 32 v's across all 1024 q (32B streaming stores).
        const float4 v0 = reinterpret_cast<const float4*>(s_row[s])[col2 * 2];
        const float4 v1 = reinterpret_cast<const float4*>(s_row[s])[col2 * 2 + 1];
        const unsigned vbase = obase + ((unsigned)s << 3);
#pragma unroll
        for (int it = 0; it < 4; ++it) {
            unsigned q = (unsigned)it * 256u + (unsigned)warp * 8u + (unsigned)qoff;
            stg_stream32(out4 + vbase + q * (FDIM / 4) + (unsigned)(col2 * 2), v0, v1);
        }
    }
}

extern "C" void kernel_launch(void* const* d_in, const int* in_sizes, int n_in,
                              void* d_out, int out_size) {
    const float* x       = (const float*)d_in[0];  // [B,F,F]
    const float* w_value = (const float*)d_in[4];  // [D,F]
    float* out = (float*)d_out;                    // [B,F,F]
    (void)in_sizes; (void)n_in; (void)out_size;

    k_wsum<<<32, 256>>>(w_value);
    k_fused<<<BDIM * (FDIM / 128), 1024>>>(x, out);
}

// round 12
// speedup vs baseline: 1.2484x; 1.0169x over previous
#include <cuda_runtime.h>
#include <cstdint>

// StochasticAttention collapses algebraically:
//   attention[b,q,v] = sum_f x[b,v,f] * (sum_d w_value[d,f])   (independent of q)
//
// Single launch. x (64MB) is re-read every graph replay -> pin in L2
// (evict_last loads). out (64MB) is write-only -> evict_first stores.
// wsum computed inline (phase 1), hidden behind the sub-chunk-0 x prefetch.

#define FDIM 1024
#define BDIM 16
#define DDIM 64

struct U4 { uint64_t a, b, c, d; };

__device__ __forceinline__ U4 ldg_pin32(const void* p) {
    U4 v;
    asm volatile("ld.global.nc.L2::evict_last.v4.b64 {%0,%1,%2,%3}, [%4];"
                 : "=l"(v.a), "=l"(v.b), "=l"(v.c), "=l"(v.d) : "l"(p));
    return v;
}
__device__ __forceinline__ void stg_stream32(void* p, float4 v0, float4 v1) {
    uint64_t a = ((uint64_t)__float_as_uint(v0.y) << 32) | __float_as_uint(v0.x);
    uint64_t b = ((uint64_t)__float_as_uint(v0.w) << 32) | __float_as_uint(v0.z);
    uint64_t c = ((uint64_t)__float_as_uint(v1.y) << 32) | __float_as_uint(v1.x);
    uint64_t d = ((uint64_t)__float_as_uint(v1.w) << 32) | __float_as_uint(v1.z);
    asm volatile("st.global.L2::evict_first.v4.b64 [%0], {%1,%2,%3,%4};"
                 :: "l"(p), "l"(a), "l"(b), "l"(c), "l"(d) : "memory");
}
__device__ __forceinline__ float flo(uint64_t u) { return __uint_as_float((unsigned)u); }
__device__ __forceinline__ float fhi(uint64_t u) { return __uint_as_float((unsigned)(u >> 32)); }

__global__ __launch_bounds__(1024, 1)
void k_fused(const float* __restrict__ x,
             const float* __restrict__ w_value,
             float* __restrict__ out) {
    __shared__ __align__(16) float4 s_part[4][FDIM / 4];  // 16 KB
    __shared__ __align__(16) float4 s_wsum[FDIM / 4];     // 4 KB
    __shared__ __align__(16) float  s_row[4][32];

    const int tid  = threadIdx.x;
    const int warp = tid >> 5;
    const int lane = tid & 31;
    const int b     = blockIdx.x >> 3;
    const int chunk = blockIdx.x & 7;

    const char* xbytes = reinterpret_cast<const char*>(x);
    const unsigned rowbase = ((unsigned)b << 10) + ((unsigned)chunk << 7);

    // ---- Prefetch sub-chunk 0 (issued before wsum phase, hides its latency) ----
    U4 a[4];
    {
        const char* xr = xbytes + (size_t)(rowbase + warp) * (FDIM * 4);
#pragma unroll
        for (int t = 0; t < 4; ++t) a[t] = ldg_pin32(xr + (t * 32 + lane) * 32);
    }

    // ---- Phase 1: wsum = column-sum of w_value [D, F] (256KB, L2-deduped) ----
    {
        const int c   = tid & 255;
        const int seg = tid >> 8;
        const float4* w4 = reinterpret_cast<const float4*>(w_value);
        float4 acc = make_float4(0.f, 0.f, 0.f, 0.f);
#pragma unroll
        for (int d = 0; d < DDIM / 4; ++d) {
            float4 v = w4[(size_t)(seg * (DDIM / 4) + d) * (FDIM / 4) + c];
            acc.x += v.x; acc.y += v.y; acc.z += v.z; acc.w += v.w;
        }
        s_part[seg][c] = acc;
    }
    __syncthreads();
    if (tid < FDIM / 4) {
        float4 p0 = s_part[0][tid], p1 = s_part[1][tid];
        float4 p2 = s_part[2][tid], p3 = s_part[3][tid];
        float4 r;
        r.x = p0.x + p1.x + p2.x + p3.x;
        r.y = p0.y + p1.y + p2.y + p3.y;
        r.z = p0.z + p1.z + p2.z + p3.z;
        r.w = p0.w + p1.w + p2.w + p3.w;
        s_wsum[tid] = r;
    }
    __syncthreads();

    // ---- Pipelined sub-chunks: 32 rows each ----
    float4* out4 = reinterpret_cast<float4*>(out);
    const int qoff = lane >> 2;          // 0..7: q-row within warp's group
    const int col2 = lane & 3;           // which 32B chunk of the 128B v-segment
    const unsigned obase = ((unsigned)b << 18) + ((unsigned)chunk << 5);

#pragma unroll
    for (int s = 0; s < 4; ++s) {
        float acc = 0.f;
#pragma unroll
        for (int t = 0; t < 4; ++t) {
            const int c = t * 32 + lane;
            float4 w0 = s_wsum[2 * c];
            float4 w1 = s_wsum[2 * c + 1];
            acc += flo(a[t].a) * w0.x + fhi(a[t].a) * w0.y
                 + flo(a[t].b) * w0.z + fhi(a[t].b) * w0.w
                 + flo(a[t].c) * w1.x + fhi(a[t].c) * w1.y
                 + flo(a[t].d) * w1.z + fhi(a[t].d) * w1.w;
        }
        if (s < 3) {
            const char* xr = xbytes + (size_t)(rowbase + (s + 1) * 32 + warp) * (FDIM * 4);
#pragma unroll
            for (int t = 0; t < 4; ++t) a[t] = ldg_pin32(xr + (t * 32 + lane) * 32);
        }
#pragma unroll
        for (int off = 16; off; off >>= 1)
            acc += __shfl_xor_sync(0xffffffffu, acc, off);
        if (lane == 0) s_row[s][warp] = acc;
        __syncthreads();

        // Broadcast these 32 v's across all 1024 q (32B streaming stores).
        const float4 v0 = reinterpret_cast<const float4*>(s_row[s])[col2 * 2];
        const float4 v1 = reinterpret_cast<const float4*>(s_row[s])[col2 * 2 + 1];
        const unsigned vbase = obase + ((unsigned)s << 3);
#pragma unroll
        for (int it = 0; it < 4; ++it) {
            unsigned q = (unsigned)it * 256u + (unsigned)warp * 8u + (unsigned)qoff;
            stg_stream32(out4 + vbase + q * (FDIM / 4) + (unsigned)(col2 * 2), v0, v1);
        }
    }
}

extern "C" void kernel_launch(void* const* d_in, const int* in_sizes, int n_in,
                              void* d_out, int out_size) {
    const float* x       = (const float*)d_in[0];  // [B,F,F]
    const float* w_value = (const float*)d_in[4];  // [D,F]
    float* out = (float*)d_out;                    // [B,F,F]
    (void)in_sizes; (void)n_in; (void)out_size;

    k_fused<<<BDIM * (FDIM / 128), 1024>>>(x, w_value, out);
}